// round 7
// baseline (speedup 1.0000x reference)
#include <cuda_runtime.h>
#include <cuda_bf16.h>

// STFT magnitude, warp-per-frame register FFT (4 CTA/SM, lean epilogue):
//   z[f] = x[2f] + i*x[2f+1]; FFT_512 = FFT16(in-reg) x FFT32(cross-lane shfl)
//   X[k] = Xe[k] + W_1024^k * Xo[k];  out[b,k,n] = |X[k]|
// Unpack twiddles (with the 0.5 factors folded in) come from a per-lane smem
// table; magnitude via x*rsqrt(x).

#define NH        512
#define CUTOFF    513
#define HOP       512
#define T_LEN     2097152
#define N_FRAMES  4095
#define BATCH     16
#define THREADS   256
#define TILE      16
#define FPW       2          // frames per warp (8 warps * 2 = 16 = TILE)
#define LD2       545        // staging row stride (513 data + swizzle pad); 545%32==1

// smem layout (floats)
#define OFF_WKTAB 0                      // float2[16][32]  W_512^{(L*j)&511}
#define OFF_STTAB 1024                   // float2[4][32]   cross-lane stage twiddles (s=0..3)
#define OFF_WUNP  1280                   // float2[16][32]  0.5*W_1024^{k1+16*brev5(L)}
#define OFF_SMAG  2304
#define SMEM_FLOATS (OFF_SMAG + TILE * LD2)   // 11024
#define SMEM_BYTES  (SMEM_FLOATS * 4)         // 44096 B  (4 CTA x 44KB fits 228KB)

// after fft16, logical U[k1] (k1 = c + 4d) lives in physical slot 4c + d:
#define SL(k1) ((((k1) & 3) << 2) | ((k1) >> 2))

__device__ __forceinline__ void cmul(float& xr, float& xi, float wr, float wi)
{
    float tr = xr * wr - xi * wi;
    xi = xr * wi + xi * wr;
    xr = tr;
}

__device__ __forceinline__ void dft4(float& r0, float& i0, float& r1, float& i1,
                                     float& r2, float& i2, float& r3, float& i3)
{
    float t0r = r0 + r2, t0i = i0 + i2;
    float t1r = r0 - r2, t1i = i0 - i2;
    float t2r = r1 + r3, t2i = i1 + i3;
    float t3r = r1 - r3, t3i = i1 - i3;
    r0 = t0r + t2r; i0 = t0i + t2i;
    r2 = t0r - t2r; i2 = t0i - t2i;
    r1 = t1r + t3i; i1 = t1i - t3r;   // X1 = t1 - i*t3
    r3 = t1r - t3i; i3 = t1i + t3r;   // X3 = t1 + i*t3
}

__device__ __forceinline__ void fft16(float* ur, float* ui)
{
    #pragma unroll
    for (int a = 0; a < 4; ++a)
        dft4(ur[a], ui[a], ur[a+4], ui[a+4], ur[a+8], ui[a+8], ur[a+12], ui[a+12]);

    const float C1 = 0.9238795325112867f, S1 = 0.3826834323650898f;
    const float R  = 0.7071067811865476f;
    cmul(ur[5],  ui[5],  C1, -S1);
    cmul(ur[6],  ui[6],  R,  -R);
    cmul(ur[7],  ui[7],  S1, -C1);
    cmul(ur[9],  ui[9],  R,  -R);
    { float tt = ur[10]; ur[10] = ui[10]; ui[10] = -tt; }
    cmul(ur[11], ui[11], -R, -R);
    cmul(ur[13], ui[13], S1, -C1);
    cmul(ur[14], ui[14], -R, -R);
    cmul(ur[15], ui[15], -C1, S1);

    #pragma unroll
    for (int c = 0; c < 4; ++c)
        dft4(ur[4*c], ui[4*c], ur[4*c+1], ui[4*c+1],
             ur[4*c+2], ui[4*c+2], ur[4*c+3], ui[4*c+3]);
}

__global__ void __launch_bounds__(THREADS, 4)
stft_mag_kernel(const float* __restrict__ x, float* __restrict__ out)
{
    extern __shared__ float sh[];
    float2* wktab = (float2*)(sh + OFF_WKTAB);   // [16][32] : [j*32 + L]
    float2* sttab = (float2*)(sh + OFF_STTAB);   // [4][32]  : [s*32 + L]
    float2* wunp  = (float2*)(sh + OFF_WUNP);    // [16][32] : [k1*32 + L]
    float*  smag  = sh + OFF_SMAG;

    const int t = threadIdx.x;
    const int w = t >> 5;
    const int L = t & 31;

    // --- build twiddle tables (once per block) ---
    for (int i = t; i < 16 * 32; i += THREADS) {
        const int j = i >> 5, l = i & 31;
        float s, c;
        sincospif(-(float)((l * j) & 511) * (1.0f / 256.0f), &s, &c);  // W_512^{l*j}
        wktab[i] = make_float2(c, s);
    }
    for (int i = t; i < 16 * 32; i += THREADS) {
        const int k1 = i >> 5, l = i & 31;
        const int rr = __brev((unsigned)l) >> 27;
        float s, c;
        sincospif(-(float)(k1 + 16 * rr) * (1.0f / 512.0f), &s, &c);   // W_1024^{k1+16r}
        wunp[i] = make_float2(0.5f * c, 0.5f * s);
    }
    if (t < 4 * 32) {
        const int s = t >> 5, l = t & 31;
        const int h = 16 >> s;
        float2 v = make_float2(1.0f, 0.0f);
        if (l & h) {
            float ss, cc;
            sincospif(-(float)((l & (h - 1)) << s) * (1.0f / 16.0f), &ss, &cc); // W_32^{..}
            v = make_float2(cc, ss);
        }
        sttab[t] = v;
    }
    __syncthreads();

    // --- per-thread constants ---
    const int r = __brev((unsigned)L) >> 27;          // this lane's k2 (DIF output order)
    const int pl0 = __brev((unsigned)((32 - r) & 31)) >> 27;

    const int b  = blockIdx.y;
    const int n0 = blockIdx.x * TILE;
    const float* rowp = x + (size_t)b * T_LEN;

    #pragma unroll 1
    for (int p = 0; p < FPW; ++p) {
        const int fl = w * FPW + p;
        const int n  = n0 + fl;
        if (n < N_FRAMES) {
            const float2* fp = (const float2*)(rowp + (size_t)n * HOP);
            float ur[16], ui[16];
            #pragma unroll
            for (int j = 0; j < 16; ++j) {               // z[L + 32j], coalesced
                float2 z = fp[L + 32 * j];
                ur[j] = z.x; ui[j] = z.y;
            }

            fft16(ur, ui);

            // U[k1] *= W_512^{L*k1}   (twiddle from shared table)
            #pragma unroll
            for (int k1 = 1; k1 < 16; ++k1) {
                float2 wv = wktab[k1 * 32 + L];
                cmul(ur[SL(k1)], ui[SL(k1)], wv.x, wv.y);
            }

            // 32-point DIF FFT across lanes: stages 0..3 general
            #pragma unroll
            for (int s = 0; s < 4; ++s) {
                const int h = 16 >> s;
                const float2 wst = sttab[s * 32 + L];
                const float sg = __uint_as_float(0x3f800000u |
                                    ((unsigned)(L & h) << (27 + s)));  // lo:+1, hi:-1
                const float cwr = wst.x, cwi = wst.y;
                #pragma unroll
                for (int q = 0; q < 16; ++q) {
                    float orr = __shfl_xor_sync(0xffffffffu, ur[q], h);
                    float ori = __shfl_xor_sync(0xffffffffu, ui[q], h);
                    float dr = fmaf(sg, ur[q], orr);
                    float di = fmaf(sg, ui[q], ori);
                    ur[q] = dr * cwr - di * cwi;
                    ui[q] = dr * cwi + di * cwr;
                }
            }
            // stage 4 (h=1): twiddle == 1 for every lane — butterfly only
            {
                const float sg = __uint_as_float(0x3f800000u |
                                    ((unsigned)(L & 1) << 31));
                #pragma unroll
                for (int q = 0; q < 16; ++q) {
                    float orr = __shfl_xor_sync(0xffffffffu, ur[q], 1);
                    float ori = __shfl_xor_sync(0xffffffffu, ui[q], 1);
                    ur[q] = fmaf(sg, ur[q], orr);
                    ui[q] = fmaf(sg, ui[q], ori);
                }
            }
            // lane L holds Z[k1 + 16*r] in slot SL(k1)

            // real-FFT unpack + magnitude -> staging tile
            //   A = Z[k], B = conj(Z[512-k]); with W' = 0.5*W_1024^k:
            //   u=Ar+Br, q=Ar-Br, p=Ai+Bi, v=Ai-Bi
            //   Xr = 0.5u + W'r*v + W'i*q ;  Xi = 0.5p - W'r*q + W'i*v
            float* col = smag + fl * LD2;
            #pragma unroll
            for (int k1 = 0; k1 < 16; ++k1) {
                const int sa = SL(k1);
                const int sb = SL((16 - k1) & 15);
                const int pl = (k1 == 0) ? pl0 : (L ^ 31);
                float Br = __shfl_sync(0xffffffffu, ur[sb], pl);
                float Bs = __shfl_sync(0xffffffffu, ui[sb], pl);   // = -Bi
                float Ar = ur[sa], Ai = ui[sa];
                float uu = Ar + Br, qq = Ar - Br;
                float pp = Ai - Bs, vv = Ai + Bs;
                float2 wv = wunp[k1 * 32 + L];
                float Xr = fmaf(wv.x, vv, fmaf(wv.y, qq, 0.5f * uu));
                float Xi = fmaf(wv.y, vv, fmaf(-wv.x, qq, 0.5f * pp));
                float s2 = fmaf(Xr, Xr, Xi * Xi);
                float mag = s2 * rsqrtf(fmaxf(s2, 1e-37f));
                const int k = k1 + 16 * r;
                col[k + (k >> 4)] = mag;                 // swizzled, conflict-free
            }
            if (L == 0)                                   // X[512] = Re(Z0) - Im(Z0)
                col[512 + 32] = fabsf(ur[0] - ui[0]);
        }
    }
    __syncthreads();

    // --- coalesced writeback: out[b, k, n0 + j] ---
    const int nvalid = min(TILE, N_FRAMES - n0);
    const size_t obase = (size_t)b * (size_t)CUTOFF * N_FRAMES + n0;
    for (int idx = t; idx < CUTOFF * TILE; idx += THREADS) {
        const int k = idx >> 4;        // / TILE
        const int j = idx & (TILE - 1);
        if (j < nvalid)
            out[obase + (size_t)k * N_FRAMES + j] = smag[j * LD2 + k + (k >> 4)];
    }
}

extern "C" void kernel_launch(void* const* d_in, const int* in_sizes, int n_in,
                              void* d_out, int out_size)
{
    const float* x = (const float*)d_in[0];
    if (n_in > 1 && in_sizes[1] > in_sizes[0]) x = (const float*)d_in[1];

    cudaFuncSetAttribute(stft_mag_kernel,
                         cudaFuncAttributeMaxDynamicSharedMemorySize, SMEM_BYTES);

    dim3 grid((N_FRAMES + TILE - 1) / TILE, BATCH);   // (256, 16)
    stft_mag_kernel<<<grid, THREADS, SMEM_BYTES>>>(x, (float*)d_out);
}